// round 7
// baseline (speedup 1.0000x reference)
#include <cuda_runtime.h>

#define BATCH 8
#define NPTS  2048
#define KNN   16
#define TPB   256
#define TILES (NPTS / TPB)      // 8 query-tiles per (cloud,batch)
#define NCB   (2 * BATCH)       // 16 (cloud,batch) groups
#define NCELL 512               // 8x8x8 Morton cells
#define NPAIR (NPTS / 2)        // 1024 point-pairs
#define NCHUNK 64               // 32-point chunks per group
#define CPP    16               // pairs per chunk

// Cell-ordered SoA pairs + per-chunk bboxes, per (cloud,batch) group.
__device__ unsigned long long g_sx[NCB * NPAIR];
__device__ unsigned long long g_sy[NCB * NPAIR];
__device__ unsigned long long g_sz[NCB * NPAIR];
__device__ float g_bbox[NCB * NCHUNK * 6];     // xmin,xmax,ymin,ymax,zmin,zmax
__device__ float g_partials[NCB * TILES];

// ---------------- f32x2 packed helpers ----------------
__device__ __forceinline__ unsigned long long x2add(unsigned long long a, unsigned long long b) {
    unsigned long long r; asm("add.rn.f32x2 %0, %1, %2;" : "=l"(r) : "l"(a), "l"(b)); return r;
}
__device__ __forceinline__ unsigned long long x2mul(unsigned long long a, unsigned long long b) {
    unsigned long long r; asm("mul.rn.f32x2 %0, %1, %2;" : "=l"(r) : "l"(a), "l"(b)); return r;
}
__device__ __forceinline__ unsigned long long x2fma(unsigned long long a, unsigned long long b,
                                                    unsigned long long c) {
    unsigned long long r; asm("fma.rn.f32x2 %0, %1, %2, %3;" : "=l"(r) : "l"(a), "l"(b), "l"(c)); return r;
}
__device__ __forceinline__ unsigned long long x2pack(float lo, float hi) {
    unsigned long long r; asm("mov.b64 %0, {%1, %2};" : "=l"(r) : "f"(lo), "f"(hi)); return r;
}
__device__ __forceinline__ void x2unpack(float& lo, float& hi, unsigned long long v) {
    asm("mov.b64 {%0, %1}, %2;" : "=f"(lo), "=f"(hi) : "l"(v));
}

__device__ __forceinline__ int spread3(int v) {
    return (v & 1) | ((v & 2) << 2) | ((v & 4) << 4);
}

// ---------------- counting sort by Morton cell + chunk bboxes ----------------
__global__ __launch_bounds__(1024)
void cellsort_kernel(const float* __restrict__ seed, const float* __restrict__ gts) {
    __shared__ int hist[NCELL];
    __shared__ int wsum[16];
    __shared__ unsigned short cellOf[NPTS];

    const int b = blockIdx.x, c = blockIdx.y;
    const int tid = threadIdx.x;
    const int lane = tid & 31, wid = tid >> 5;
    const int g = c * BATCH + b;
    const float* __restrict__ src = (c == 0 ? seed : gts) + (size_t)b * NPTS * 3;

    if (tid < NCELL) hist[tid] = 0;
    __syncthreads();

    for (int p = tid; p < NPTS; p += 1024) {
        const float x = src[3*p+0], y = src[3*p+1], z = src[3*p+2];
        int bx = (int)floorf((x + 3.0f) * (8.0f / 6.0f));
        int by = (int)floorf((y + 3.0f) * (8.0f / 6.0f));
        int bz = (int)floorf((z + 3.0f) * (8.0f / 6.0f));
        bx = min(max(bx, 0), 7); by = min(max(by, 0), 7); bz = min(max(bz, 0), 7);
        const int cell = spread3(bx) | (spread3(by) << 1) | (spread3(bz) << 2);
        cellOf[p] = (unsigned short)cell;
        atomicAdd(&hist[cell], 1);
    }
    __syncthreads();

    int a = 0, s = 0;
    if (tid < NCELL) {
        a = hist[tid]; s = a;
#pragma unroll
        for (int off = 1; off < 32; off <<= 1) {
            const int n = __shfl_up_sync(0xffffffffu, s, off);
            if (lane >= off) s += n;
        }
        if (lane == 31) wsum[wid] = s;
    }
    __syncthreads();
    if (tid < 16) {
        int w = wsum[tid];
#pragma unroll
        for (int off = 1; off < 16; off <<= 1) {
            const int n = __shfl_up_sync(0xffffu, w, off, 16);
            if (tid >= off) w += n;
        }
        wsum[tid] = w;
    }
    __syncthreads();
    if (tid < NCELL) hist[tid] = (wid ? wsum[wid - 1] : 0) + s - a;
    __syncthreads();

    // scatter (within-cell order arbitrary; all downstream sums are permutation-invariant)
    float* __restrict__ dx = (float*)(g_sx + g * NPAIR);
    float* __restrict__ dy = (float*)(g_sy + g * NPAIR);
    float* __restrict__ dz = (float*)(g_sz + g * NPAIR);
    for (int p = tid; p < NPTS; p += 1024) {
        const float x = src[3*p+0], y = src[3*p+1], z = src[3*p+2];   // L1-hot
        const int pos = atomicAdd(&hist[cellOf[p]], 1);
        dx[pos] = x; dy[pos] = y; dz[pos] = z;
    }
    __syncthreads();

    // per-chunk bbox: 32 warps, each owns 2 chunks; warp butterfly min/max
#pragma unroll
    for (int rep = 0; rep < 2; ++rep) {
        const int ch = wid + rep * 32;
        const int p = ch * 32 + lane;
        float xn = dx[p], yn = dy[p], zn = dz[p];
        float xm = xn, ym = yn, zm = zn;
#pragma unroll
        for (int off = 16; off > 0; off >>= 1) {
            xn = fminf(xn, __shfl_xor_sync(0xffffffffu, xn, off));
            xm = fmaxf(xm, __shfl_xor_sync(0xffffffffu, xm, off));
            yn = fminf(yn, __shfl_xor_sync(0xffffffffu, yn, off));
            ym = fmaxf(ym, __shfl_xor_sync(0xffffffffu, ym, off));
            zn = fminf(zn, __shfl_xor_sync(0xffffffffu, zn, off));
            zm = fmaxf(zm, __shfl_xor_sync(0xffffffffu, zm, off));
        }
        if (lane == 0) {
            float* bb = g_bbox + (g * NCHUNK + ch) * 6;
            bb[0] = xn; bb[1] = xm; bb[2] = yn; bb[3] = ym; bb[4] = zn; bb[5] = zm;
        }
    }
}

// depth-2 parallel sorted-ascending insert
#define INS(dv) do {                                                      \
    _Pragma("unroll")                                                     \
    for (int k = KNN - 1; k >= 1; --k)                                    \
        r[k] = fminf(r[k], fmaxf(r[k-1], (dv)));                          \
    r[0] = fminf(r[0], (dv));                                             \
} while (0)

#define PAIR_BODY(jp) do {                                                \
    const unsigned long long X = sx[jp], Y = sy[jp], Z = sz[jp];          \
    const unsigned long long ddx = x2add(X, npx);                         \
    const unsigned long long ddy = x2add(Y, npy);                         \
    const unsigned long long ddz = x2add(Z, npz);                         \
    const unsigned long long d2 =                                         \
        x2fma(ddx, ddx, x2fma(ddy, ddy, x2mul(ddz, ddz)));                \
    float dA, dB; x2unpack(dA, dB, d2);                                   \
    if (fminf(dA, dB) < r[KNN-1]) { INS(dA); INS(dB); }                   \
} while (0)

// ---------------- knn: chunk-bbox pruned scan, anchored at own chunk ----------------
__global__ __launch_bounds__(TPB, 1)
void knn_kernel() {
    __shared__ unsigned long long sx[NPAIR];   // 8 KB each
    __shared__ unsigned long long sy[NPAIR];
    __shared__ unsigned long long sz[NPAIR];
    __shared__ float sbb[NCHUNK * 6];          // 1.5 KB
    __shared__ float red[TPB / 32];

    const int tile = blockIdx.x, b = blockIdx.y, c = blockIdx.z;
    const int tid = threadIdx.x;
    const int lane = tid & 31, wid = tid >> 5;
    const int g = (c * BATCH + b);

    for (int j = tid; j < NPAIR; j += TPB) {
        sx[j] = g_sx[g * NPAIR + j];
        sy[j] = g_sy[g * NPAIR + j];
        sz[j] = g_sz[g * NPAIR + j];
    }
    for (int j = tid; j < NCHUNK * 6; j += TPB)
        sbb[j] = g_bbox[g * NCHUNK * 6 + j];
    __syncthreads();

    // query point: position tile*TPB + tid in sorted order
    const int p = tile * TPB + tid;
    float qx, qy, qz, hx, hy, hz;
    x2unpack(qx, hx, sx[p >> 1]);
    x2unpack(qy, hy, sy[p >> 1]);
    x2unpack(qz, hz, sz[p >> 1]);
    if (p & 1) { qx = hx; qy = hy; qz = hz; }
    const unsigned long long npx = x2pack(-qx, -qx);
    const unsigned long long npy = x2pack(-qy, -qy);
    const unsigned long long npz = x2pack(-qz, -qz);

    float r[KNN];
#pragma unroll
    for (int k = 0; k < KNN; k++) r[k] = 3.0e38f;

    // scan chunks starting at this warp's own chunk (dmin=0 there -> fast warm-up)
    const int sc0 = tile * (TPB / 32) + wid;
    for (int ss = 0; ss < NCHUNK; ++ss) {
        const int sc = (sc0 + ss) & (NCHUNK - 1);
        const float bxn = sbb[sc*6+0], bxm = sbb[sc*6+1];
        const float byn = sbb[sc*6+2], bym = sbb[sc*6+3];
        const float bzn = sbb[sc*6+4], bzm = sbb[sc*6+5];
        const float ex = fmaxf(fmaxf(bxn - qx, qx - bxm), 0.0f);
        const float ey = fmaxf(fmaxf(byn - qy, qy - bym), 0.0f);
        const float ez = fmaxf(fmaxf(bzn - qz, qz - bzm), 0.0f);
        const float dmin2 = fmaf(ex, ex, fmaf(ey, ey, ez * ez));
        if (__any_sync(0xffffffffu, dmin2 < r[KNN - 1])) {
            const int jp0 = sc * CPP;
#pragma unroll 4
            for (int t = 0; t < CPP; ++t) PAIR_BODY(jp0 + t);
        }
    }

    float s16 = 0.0f;
#pragma unroll
    for (int k = 0; k < KNN; k++) s16 += r[k];

#pragma unroll
    for (int off = 16; off > 0; off >>= 1)
        s16 += __shfl_down_sync(0xffffffffu, s16, off);
    if (lane == 0) red[wid] = s16;
    __syncthreads();
    if (tid == 0) {
        float bs = 0.0f;
#pragma unroll
        for (int w = 0; w < TPB / 32; w++) bs += red[w];
        g_partials[g * TILES + tile] = bs;
    }
}

// ---------------- finish: 128 partials -> loss ----------------
__global__ __launch_bounds__(128)
void finish_kernel(float* __restrict__ out) {
    __shared__ float ws[NCB];
    const int tid = threadIdx.x;

    float v = g_partials[tid];          // group = tid>>3 (TILES=8 partials each)
#pragma unroll
    for (int off = 4; off > 0; off >>= 1)
        v += __shfl_down_sync(0xffffffffu, v, off, 8);
    if ((tid & 7) == 0) ws[tid >> 3] = v;
    __syncthreads();

    if (tid == 0) {
        const double norm = 1.0 / ((double)NPTS * (double)KNN);
        double loss = 0.0;
        for (int g = 0; g < BATCH; ++g) {
            const double diff = ((double)ws[g] - (double)ws[BATCH + g]) * norm;
            loss += diff * diff;
        }
        out[0] = (float)(loss / (double)BATCH);
    }
}

extern "C" void kernel_launch(void* const* d_in, const int* in_sizes, int n_in,
                              void* d_out, int out_size) {
    const float* seed = (const float*)d_in[0];
    const float* gts  = (const float*)d_in[1];
    float* out = (float*)d_out;

    dim3 gsort(BATCH, 2);
    cellsort_kernel<<<gsort, 1024>>>(seed, gts);

    dim3 gknn(TILES, BATCH, 2);
    knn_kernel<<<gknn, TPB>>>();

    finish_kernel<<<1, 128>>>(out);
}